// round 1
// baseline (speedup 1.0000x reference)
#include <cuda_runtime.h>
#include <math.h>

#define B_    16384
#define D_    4096
#define H_    2048
#define E_    64
#define TEMP  0.8f

// Scratch (allocation-free rule: __device__ globals)
__device__ float g_h[(size_t)B_ * H_];     // 128 MB hidden activations
__device__ float g_ent[B_];                // per-row entropy

// ---------------------------------------------------------------------------
// GEMM1: h = relu(x @ W1^T + b1)   x:[B,D] row-major, W1:[H,D] row-major
// 128x128 tile, BK=16, 256 threads, 8x8 per-thread microtile, fp32 FFMA.
// ---------------------------------------------------------------------------
__global__ void __launch_bounds__(256, 2)
gemm1_relu(const float* __restrict__ x, const float* __restrict__ W1,
           const float* __restrict__ b1)
{
    __shared__ float As[16][128];   // As[k][m]
    __shared__ float Bs[16][128];   // Bs[k][n]

    const int tid = threadIdx.x;
    const int bm  = blockIdx.y * 128;
    const int bn  = blockIdx.x * 128;
    const int tx  = tid & 15;       // 0..15 -> n microtile
    const int ty  = tid >> 4;       // 0..15 -> m microtile
    const int lr  = tid >> 2;       // 0..63 loader row
    const int lc  = (tid & 3) << 2; // 0,4,8,12 loader col (float4)

    float acc[8][8];
#pragma unroll
    for (int i = 0; i < 8; i++)
#pragma unroll
        for (int j = 0; j < 8; j++) acc[i][j] = 0.f;

    const float* xp = x  + (size_t)(bm + lr) * D_ + lc;
    const float* wp = W1 + (size_t)(bn + lr) * D_ + lc;

    for (int k0 = 0; k0 < D_; k0 += 16) {
#pragma unroll
        for (int i = 0; i < 2; i++) {
            const int r = lr + i * 64;
            float4 v = *(const float4*)(xp + (size_t)i * 64 * D_ + k0);
            As[lc + 0][r] = v.x; As[lc + 1][r] = v.y;
            As[lc + 2][r] = v.z; As[lc + 3][r] = v.w;
            float4 w = *(const float4*)(wp + (size_t)i * 64 * D_ + k0);
            Bs[lc + 0][r] = w.x; Bs[lc + 1][r] = w.y;
            Bs[lc + 2][r] = w.z; Bs[lc + 3][r] = w.w;
        }
        __syncthreads();

#pragma unroll
        for (int k = 0; k < 16; k++) {
            float a[8], bb[8];
            *(float4*)&a[0]  = *(const float4*)&As[k][ty * 8];
            *(float4*)&a[4]  = *(const float4*)&As[k][ty * 8 + 4];
            *(float4*)&bb[0] = *(const float4*)&Bs[k][tx * 8];
            *(float4*)&bb[4] = *(const float4*)&Bs[k][tx * 8 + 4];
#pragma unroll
            for (int i = 0; i < 8; i++)
#pragma unroll
                for (int j = 0; j < 8; j++)
                    acc[i][j] = fmaf(a[i], bb[j], acc[i][j]);
        }
        __syncthreads();
    }

#pragma unroll
    for (int i = 0; i < 8; i++) {
        const int row = bm + ty * 8 + i;
#pragma unroll
        for (int j = 0; j < 8; j++) {
            const int col = bn + tx * 8 + j;
            float v = acc[i][j] + b1[col];
            g_h[(size_t)row * H_ + col] = v > 0.f ? v : 0.f;
        }
    }
}

// ---------------------------------------------------------------------------
// Router: per-row logits (64 experts), temp softmax, top-2 (JAX tie-break:
// lower index wins), normalized weights, unscaled-softmax entropy.
// One CTA (256 threads) per row. W2 (512 KB) stays L2-resident.
// Output layout: [rw (B*2) | idx-as-float (B*2) | uncertainty (1)]
// ---------------------------------------------------------------------------
__global__ void __launch_bounds__(256)
router_kernel(const float* __restrict__ W2, const float* __restrict__ b2,
              float* __restrict__ out)
{
    __shared__ float4 sh_h[512];      // 2048 floats = one h row
    __shared__ float  sh_part[256];
    __shared__ float  sh_logit[64];

    const int b   = blockIdx.x;
    const int tid = threadIdx.x;

    const float4* hr = (const float4*)(g_h + (size_t)b * H_);
    sh_h[tid]       = hr[tid];
    sh_h[tid + 256] = hr[tid + 256];
    __syncthreads();

    // 4 threads per expert: expert e = tid>>2, chunk q = tid&3 (128 float4 each)
    const int e = tid >> 2;
    const int q = tid & 3;
    const float4* w  = (const float4*)(W2 + (size_t)e * H_) + q * 128;
    const float4* hh = sh_h + q * 128;
    float s = 0.f;
#pragma unroll 4
    for (int i = 0; i < 128; i++) {
        float4 wv = w[i], hv = hh[i];
        s += wv.x * hv.x + wv.y * hv.y + wv.z * hv.z + wv.w * hv.w;
    }
    sh_part[tid] = s;
    __syncthreads();

    if (tid < 64) {
        sh_logit[tid] = sh_part[tid * 4] + sh_part[tid * 4 + 1]
                      + sh_part[tid * 4 + 2] + sh_part[tid * 4 + 3] + b2[tid];
    }
    __syncthreads();

    if (tid < 32) {
        const float l0 = sh_logit[tid];
        const float l1 = sh_logit[tid + 32];

        // ---- top-1 argmax (tie -> lower index) ----
        float v; int idx;
        if (l0 >= l1) { v = l0; idx = tid; } else { v = l1; idx = tid + 32; }
#pragma unroll
        for (int o = 16; o; o >>= 1) {
            float ov = __shfl_xor_sync(0xffffffffu, v,   o);
            int   oi = __shfl_xor_sync(0xffffffffu, idx, o);
            if (ov > v || (ov == v && oi < idx)) { v = ov; idx = oi; }
        }
        const float v1 = v; const int i1 = idx;
        const float m  = v1;   // true max of the 64 logits

        // ---- top-2: mask out i1, argmax again ----
        const float c0 = (tid      == i1) ? -INFINITY : l0;
        const float c1 = (tid + 32 == i1) ? -INFINITY : l1;
        if (c0 >= c1) { v = c0; idx = tid; } else { v = c1; idx = tid + 32; }
#pragma unroll
        for (int o = 16; o; o >>= 1) {
            float ov = __shfl_xor_sync(0xffffffffu, v,   o);
            int   oi = __shfl_xor_sync(0xffffffffu, idx, o);
            if (ov > v || (ov == v && oi < idx)) { v = ov; idx = oi; }
        }
        const float v2 = v; const int i2 = idx;

        // ---- entropy from UN-scaled softmax ----
        const float z0 = expf(l0 - m);
        const float z1 = expf(l1 - m);
        float Z = z0 + z1;
#pragma unroll
        for (int o = 16; o; o >>= 1) Z += __shfl_xor_sync(0xffffffffu, Z, o);
        const float q0 = z0 / Z, q1 = z1 / Z;
        float ec = -(q0 * logf(q0 + 1e-10f) + q1 * logf(q1 + 1e-10f));
#pragma unroll
        for (int o = 16; o; o >>= 1) ec += __shfl_xor_sync(0xffffffffu, ec, o);

        if (tid == 0) {
            // normalized top-2 weights: denominators of the temp-softmax cancel
            const float r = 1.f / (1.f + expf((v2 - v1) / TEMP));
            out[b * 2 + 0] = r;
            out[b * 2 + 1] = 1.f - r;
            out[(size_t)B_ * 2 + b * 2 + 0] = (float)i1;
            out[(size_t)B_ * 2 + b * 2 + 1] = (float)i2;
            g_ent[b] = ec;
        }
    }
}

// ---------------------------------------------------------------------------
// Deterministic entropy mean -> uncertainty scalar at out[4*B_]
// ---------------------------------------------------------------------------
__global__ void __launch_bounds__(256)
reduce_ent(float* __restrict__ out)
{
    __shared__ float sh[256];
    const int t = threadIdx.x;
    float s = 0.f;
    const float* p = g_ent + t * 64;
    for (int i = 0; i < 64; i++) s += p[i];     // fixed sequential order
    sh[t] = s;
    __syncthreads();
    for (int off = 128; off > 0; off >>= 1) {   // fixed tree order
        if (t < off) sh[t] += sh[t + off];
        __syncthreads();
    }
    if (t == 0)
        out[(size_t)4 * B_] = (sh[0] / (float)B_) / logf((float)E_);
}

// ---------------------------------------------------------------------------
extern "C" void kernel_launch(void* const* d_in, const int* in_sizes, int n_in,
                              void* d_out, int out_size)
{
    const float* x  = (const float*)d_in[0];
    const float* W1 = (const float*)d_in[1];
    const float* b1 = (const float*)d_in[2];
    const float* W2 = (const float*)d_in[3];
    const float* b2 = (const float*)d_in[4];
    float* out = (float*)d_out;

    dim3 g1(H_ / 128, B_ / 128);          // 16 x 128 = 2048 CTAs
    gemm1_relu<<<g1, 256>>>(x, W1, b1);
    router_kernel<<<B_, 256>>>(W2, b2, out);
    reduce_ent<<<1, 256>>>(out);
}

// round 5
// speedup vs baseline: 3.3331x; 3.3331x over previous
#include <cuda_runtime.h>
#include <cuda_fp16.h>
#include <math.h>
#include <stdint.h>

#define B_    16384
#define D_    4096
#define H_    2048
#define E_    64
#define TEMP  0.8f

// ---------------------------------------------------------------------------
// Scratch (__device__ globals; allocation-free rule)
// ---------------------------------------------------------------------------
__device__ __half g_xhi [(size_t)B_ * D_];
__device__ __half g_xmid[(size_t)B_ * D_];
__device__ __half g_whi [(size_t)H_ * D_];
__device__ __half g_wmid[(size_t)H_ * D_];
__device__ float g_plog[(size_t)32 * B_ * E_];   // partial logits [p][b][e]
__device__ float g_ent[B_];

// ---------------------------------------------------------------------------
// PTX helpers — base sm_103 features only (NO tcgen05/TMA: 'a'-suffix gated)
// ---------------------------------------------------------------------------
__device__ __forceinline__ uint32_t smem_u32(const void* p) {
    uint32_t r;
    asm("{ .reg .u64 t; cvta.to.shared.u64 t, %1; cvt.u32.u64 %0, t; }"
        : "=r"(r) : "l"(p));
    return r;
}

#define CP_ASYNC16(smem, gptr) \
    asm volatile("cp.async.cg.shared.global [%0], [%1], 16;" \
                 :: "r"(smem), "l"(gptr) : "memory")
#define CP_COMMIT() asm volatile("cp.async.commit_group;" ::: "memory")
#define CP_WAIT1()  asm volatile("cp.async.wait_group 1;" ::: "memory")

#define LDSM4(R, addr) \
    asm volatile("ldmatrix.sync.aligned.m8n8.x4.shared.b16 {%0,%1,%2,%3}, [%4];" \
                 : "=r"((R)[0]), "=r"((R)[1]), "=r"((R)[2]), "=r"((R)[3]) \
                 : "r"(addr))

#define MMA16816(Dv, Av, B0, B1) \
    asm volatile("mma.sync.aligned.m16n8k16.row.col.f32.f16.f16.f32 " \
                 "{%0,%1,%2,%3}, {%4,%5,%6,%7}, {%8,%9}, {%0,%1,%2,%3};" \
                 : "+f"((Dv)[0]), "+f"((Dv)[1]), "+f"((Dv)[2]), "+f"((Dv)[3]) \
                 : "r"((Av)[0]), "r"((Av)[1]), "r"((Av)[2]), "r"((Av)[3]), \
                   "r"(B0), "r"(B1))

// swizzled offset inside a [128 rows][32 halves] fp16 tile (64B rows, 16B chunks)
__device__ __forceinline__ uint32_t swz(int r, int c) {
    return (uint32_t)(r * 64 + ((c ^ ((r >> 1) & 3)) << 4));
}
// ldmatrix per-lane address inside a tile (A: rows=m, B: rows=n; same pattern)
__device__ __forceinline__ uint32_t ldsm_addr(uint32_t tile_base, int row0,
                                              int k16, int lane) {
    int r = row0 + (lane & 15);
    int c = k16 * 2 + (lane >> 4);
    return tile_base + swz(r, c);
}

// ---------------------------------------------------------------------------
// Split fp32 -> fp16 hi/mid (dropped products ~u^2 ~ 2.4e-7, below fp32 noise)
// ---------------------------------------------------------------------------
__device__ __forceinline__ uint32_t pk2(__half a, __half b) {
    return (uint32_t)__half_as_ushort(a) | ((uint32_t)__half_as_ushort(b) << 16);
}

__global__ void __launch_bounds__(256)
split_x(const float* __restrict__ x) {
    const int i = blockIdx.x * 256 + threadIdx.x;        // float4 index
    float4 v = ((const float4*)x)[i];
    __half h0 = __float2half_rn(v.x), h1 = __float2half_rn(v.y);
    __half h2 = __float2half_rn(v.z), h3 = __float2half_rn(v.w);
    __half m0 = __float2half_rn(v.x - __half2float(h0));
    __half m1 = __float2half_rn(v.y - __half2float(h1));
    __half m2 = __float2half_rn(v.z - __half2float(h2));
    __half m3 = __float2half_rn(v.w - __half2float(h3));
    ((uint2*)g_xhi )[i] = make_uint2(pk2(h0, h1), pk2(h2, h3));
    ((uint2*)g_xmid)[i] = make_uint2(pk2(m0, m1), pk2(m2, m3));
}

__global__ void __launch_bounds__(256)
split_w(const float* __restrict__ W1) {
    const int i = blockIdx.x * 256 + threadIdx.x;
    float4 v = ((const float4*)W1)[i];
    __half h0 = __float2half_rn(v.x), h1 = __float2half_rn(v.y);
    __half h2 = __float2half_rn(v.z), h3 = __float2half_rn(v.w);
    __half m0 = __float2half_rn(v.x - __half2float(h0));
    __half m1 = __float2half_rn(v.y - __half2float(h1));
    __half m2 = __float2half_rn(v.z - __half2float(h2));
    __half m3 = __float2half_rn(v.w - __half2float(h3));
    ((uint2*)g_whi )[i] = make_uint2(pk2(h0, h1), pk2(h2, h3));
    ((uint2*)g_wmid)[i] = make_uint2(pk2(m0, m1), pk2(m2, m3));
}

// ---------------------------------------------------------------------------
// GEMM1 fp16x3 mma.sync, 128x128 tile, K-slab 32, 3-stage cp.async pipeline.
// Fused bias + ReLU + partial GEMM2 epilogue into g_plog.
// Grid: (16 col-blocks, 128 row-blocks), 256 threads = 8 warps (4 M x 2 N).
// SMEM stage: [A hi|A mid|B hi|B mid] each [128][32] fp16 = 8KB -> 32KB/stage.
// ---------------------------------------------------------------------------
#define STAGE_BYTES 32768
#define SMEM_TOTAL_DYN 100352   // max(3*32768, 128*132*4 + 64*128*4)

__device__ __forceinline__ void load_slab(int s, int bm, int bn,
                                          uint32_t smem_u, int tid) {
    if (s < 128) {
        const uint32_t st = smem_u + (s % 3) * STAGE_BYTES;
        const int k0 = s * 32;
        const int rsub = tid >> 2;          // 0..63
        const int cc = tid & 3;
#pragma unroll
        for (int q = 0; q < 8; ++q) {
            const int isB   = q >> 2;
            const int split = (q >> 1) & 1;
            const int rr    = ((q & 1) << 6) + rsub;   // 0..127
            const __half* src;
            if (isB) src = split ? g_wmid : g_whi;
            else     src = split ? g_xmid : g_xhi;
            const int rowbase = isB ? bn : bm;
            const __half* g = src + (size_t)(rowbase + rr) * D_ + k0 + cc * 8;
            uint32_t dst = st + isB * 16384 + split * 8192 + swz(rr, cc);
            CP_ASYNC16(dst, g);
        }
    }
    CP_COMMIT();
}

__global__ void __launch_bounds__(256, 1)
gemm_mma(const float* __restrict__ b1, const float* __restrict__ W2)
{
    extern __shared__ char dsm[];
    __shared__ float b1s[128];

    const int tid  = threadIdx.x;
    const int wid  = tid >> 5;
    const int lane = tid & 31;
    const int wm   = wid & 3;          // 4 warps in M
    const int wn   = wid >> 2;         // 2 warps in N
    const int bm   = blockIdx.y * 128;
    const int bn   = blockIdx.x * 128;
    const uint32_t smem_u = smem_u32(dsm);

    if (tid < 128) b1s[tid] = b1[bn + tid];

    float acc[2][8][4];
#pragma unroll
    for (int i = 0; i < 2; ++i)
#pragma unroll
        for (int j = 0; j < 8; ++j)
#pragma unroll
            for (int k = 0; k < 4; ++k) acc[i][j][k] = 0.f;

    load_slab(0, bm, bn, smem_u, tid);
    load_slab(1, bm, bn, smem_u, tid);

    for (int s = 0; s < 128; ++s) {
        CP_WAIT1();
        __syncthreads();
        load_slab(s + 2, bm, bn, smem_u, tid);

        const uint32_t sb = smem_u + (s % 3) * STAGE_BYTES;
#pragma unroll
        for (int k16 = 0; k16 < 2; ++k16) {
            uint32_t ah[2][4], am[2][4];
#pragma unroll
            for (int i = 0; i < 2; ++i) {
                LDSM4(ah[i], ldsm_addr(sb,        wm * 32 + i * 16, k16, lane));
                LDSM4(am[i], ldsm_addr(sb + 8192, wm * 32 + i * 16, k16, lane));
            }
#pragma unroll
            for (int n16 = 0; n16 < 4; ++n16) {
                uint32_t bh[4], bmid[4];
                LDSM4(bh,   ldsm_addr(sb + 16384,        wn * 64 + n16 * 16, k16, lane));
                LDSM4(bmid, ldsm_addr(sb + 16384 + 8192, wn * 64 + n16 * 16, k16, lane));
#pragma unroll
                for (int i = 0; i < 2; ++i) {
                    MMA16816(acc[i][2 * n16],     ah[i], bh[0],   bh[2]);
                    MMA16816(acc[i][2 * n16],     ah[i], bmid[0], bmid[2]);
                    MMA16816(acc[i][2 * n16],     am[i], bh[0],   bh[2]);
                    MMA16816(acc[i][2 * n16 + 1], ah[i], bh[1],   bh[3]);
                    MMA16816(acc[i][2 * n16 + 1], ah[i], bmid[1], bmid[3]);
                    MMA16816(acc[i][2 * n16 + 1], am[i], bh[1],   bh[3]);
                }
            }
        }
    }

    // ---- epilogue: accums -> SMEM h tile (bias + relu) ----
    __syncthreads();                    // everyone done with stage buffers
    float* hT = (float*)dsm;            // [128][132] fp32
    const int g  = lane >> 2;
    const int t4 = lane & 3;
#pragma unroll
    for (int i = 0; i < 2; ++i) {
        const int r0 = wm * 32 + i * 16 + g;
#pragma unroll
        for (int j = 0; j < 8; ++j) {
            const int c = wn * 64 + j * 8 + t4 * 2;
            float v0 = acc[i][j][0] + b1s[c];
            float v1 = acc[i][j][1] + b1s[c + 1];
            float v2 = acc[i][j][2] + b1s[c];
            float v3 = acc[i][j][3] + b1s[c + 1];
            v0 = v0 > 0.f ? v0 : 0.f;  v1 = v1 > 0.f ? v1 : 0.f;
            v2 = v2 > 0.f ? v2 : 0.f;  v3 = v3 > 0.f ? v3 : 0.f;
            *(float2*)&hT[(size_t)r0 * 132 + c]       = make_float2(v0, v1);
            *(float2*)&hT[(size_t)(r0 + 8) * 132 + c] = make_float2(v2, v3);
        }
    }

    // ---- W2 chunk into SMEM ----
    float* W2s = (float*)(dsm + 67584);            // [64][128] fp32
#pragma unroll
    for (int q = 0; q < 8; ++q) {
        const int id = q * 256 + tid;              // float4 index 0..2047
        ((float4*)W2s)[id] =
            *(const float4*)(W2 + (size_t)(id >> 5) * H_ + bn + (id & 31) * 4);
    }
    __syncthreads();

    // ---- per-thread partial logits: 64 experts x 64 cols ----
    const int half = tid >> 7;          // 0/1 -> N half
    const int row  = tid & 127;
    const int ch   = half * 64;

    float h[64];
#pragma unroll
    for (int j = 0; j < 16; ++j)
        *(float4*)&h[j * 4] = *(float4*)&hT[(size_t)row * 132 + ch + j * 4];

    float* dst = g_plog + ((size_t)(blockIdx.x * 2 + half) * B_ + (bm + row)) * 64;
#pragma unroll
    for (int eg = 0; eg < 2; ++eg) {
        __align__(16) float accv[32];
#pragma unroll
        for (int e2 = 0; e2 < 32; ++e2) {
            const float4* wr = (const float4*)(W2s + (eg * 32 + e2) * 128 + ch);
            float a = 0.f;
#pragma unroll
            for (int j = 0; j < 16; ++j) {
                float4 wv = wr[j];
                a += h[j*4+0]*wv.x + h[j*4+1]*wv.y + h[j*4+2]*wv.z + h[j*4+3]*wv.w;
            }
            accv[e2] = a;
        }
#pragma unroll
        for (int q = 0; q < 8; ++q)
            ((float4*)(dst + eg * 32))[q] = *(float4*)&accv[q * 4];
    }
}

// ---------------------------------------------------------------------------
// Final router: sum 32 partial-logit slabs, temp softmax top-2, entropy.
// One warp per row; 8 rows per CTA.
// ---------------------------------------------------------------------------
__global__ void __launch_bounds__(256)
router_final(const float* __restrict__ b2, float* __restrict__ out)
{
    const int warp = threadIdx.x >> 5;
    const int lane = threadIdx.x & 31;
    const int b = blockIdx.x * 8 + warp;

    float l0 = b2[lane], l1 = b2[lane + 32];
    const float* p = g_plog + (size_t)b * 64;
#pragma unroll 8
    for (int q = 0; q < 32; ++q) {
        l0 += p[(size_t)q * B_ * 64 + lane];
        l1 += p[(size_t)q * B_ * 64 + lane + 32];
    }

    // ---- top-1 argmax (tie -> lower index) ----
    float v; int idx;
    if (l0 >= l1) { v = l0; idx = lane; } else { v = l1; idx = lane + 32; }
#pragma unroll
    for (int o = 16; o; o >>= 1) {
        float ov = __shfl_xor_sync(0xffffffffu, v,   o);
        int   oi = __shfl_xor_sync(0xffffffffu, idx, o);
        if (ov > v || (ov == v && oi < idx)) { v = ov; idx = oi; }
    }
    const float v1 = v; const int i1 = idx;
    const float m  = v1;

    // ---- top-2: mask i1, argmax again ----
    const float c0 = (lane      == i1) ? -INFINITY : l0;
    const float c1 = (lane + 32 == i1) ? -INFINITY : l1;
    if (c0 >= c1) { v = c0; idx = lane; } else { v = c1; idx = lane + 32; }
#pragma unroll
    for (int o = 16; o; o >>= 1) {
        float ov = __shfl_xor_sync(0xffffffffu, v,   o);
        int   oi = __shfl_xor_sync(0xffffffffu, idx, o);
        if (ov > v || (ov == v && oi < idx)) { v = ov; idx = oi; }
    }
    const float v2 = v; const int i2 = idx;

    // ---- entropy from UN-scaled softmax ----
    const float z0 = expf(l0 - m);
    const float z1 = expf(l1 - m);
    float Z = z0 + z1;
#pragma unroll
    for (int o = 16; o; o >>= 1) Z += __shfl_xor_sync(0xffffffffu, Z, o);
    const float q0 = z0 / Z, q1 = z1 / Z;
    float ec = -(q0 * logf(q0 + 1e-10f) + q1 * logf(q1 + 1e-10f));
#pragma unroll
    for (int o = 16; o; o >>= 1) ec += __shfl_xor_sync(0xffffffffu, ec, o);

    if (lane == 0) {
        const float r = 1.f / (1.f + expf((v2 - v1) / TEMP));
        out[b * 2 + 0] = r;
        out[b * 2 + 1] = 1.f - r;
        out[(size_t)B_ * 2 + b * 2 + 0] = (float)i1;
        out[(size_t)B_ * 2 + b * 2 + 1] = (float)i2;
        g_ent[b] = ec;
    }
}

// ---------------------------------------------------------------------------
// Deterministic entropy mean -> uncertainty scalar at out[4*B_]
// ---------------------------------------------------------------------------
__global__ void __launch_bounds__(256)
reduce_ent(float* __restrict__ out)
{
    __shared__ float sh[256];
    const int t = threadIdx.x;
    float s = 0.f;
    const float* p = g_ent + t * 64;
    for (int i = 0; i < 64; i++) s += p[i];
    sh[t] = s;
    __syncthreads();
    for (int off = 128; off > 0; off >>= 1) {
        if (t < off) sh[t] += sh[t + off];
        __syncthreads();
    }
    if (t == 0)
        out[(size_t)4 * B_] = (sh[0] / (float)B_) / logf((float)E_);
}

// ---------------------------------------------------------------------------
extern "C" void kernel_launch(void* const* d_in, const int* in_sizes, int n_in,
                              void* d_out, int out_size)
{
    const float* x  = (const float*)d_in[0];
    const float* W1 = (const float*)d_in[1];
    const float* b1 = (const float*)d_in[2];
    const float* W2 = (const float*)d_in[3];
    const float* b2 = (const float*)d_in[4];
    float* out = (float*)d_out;

    cudaFuncSetAttribute(gemm_mma, cudaFuncAttributeMaxDynamicSharedMemorySize,
                         SMEM_TOTAL_DYN);

    split_x<<<65536, 256>>>(x);                 // B*D/4 float4s
    split_w<<<8192, 256>>>(W1);                 // H*D/4 float4s
    gemm_mma<<<dim3(16, 128), 256, SMEM_TOTAL_DYN>>>(b1, W2);
    router_final<<<2048, 256>>>(b2, out);
    reduce_ent<<<1, 256>>>(out);
}